// round 15
// baseline (speedup 1.0000x reference)
#include <cuda_runtime.h>
#include <cuda_fp16.h>
#include <cstdint>
#include <cstddef>

#define N_ITEM 81920
#define E_INT 327680
#define N_TGT 2048
#define NUM_NODE 50000
#define DIM 256
#define NPOS 200
#define ALPHA 0.2f

// ---------------- device scratch (static, no allocation) ----------------
__device__ __align__(16) __half g_ft_hi[(size_t)N_ITEM * DIM];
__device__ int   g_deg[N_ITEM];
__device__ int   g_rowoff[N_ITEM + 1];
__device__ int   g_cursor[N_ITEM];
__device__ int   g_esrc[E_INT];
__device__ int   g_adeg[N_TGT];
__device__ int   g_arowoff[N_TGT + 1];
__device__ int   g_acursor[N_TGT];
__device__ int   g_aperm[N_ITEM];
__device__ int   g_bsum[328];
__device__ int   g_boff[328];
__device__ __align__(16) float g_B[NPOS * DIM];
__device__ float g_cpart[4][N_ITEM];
__device__ __align__(16) __half g_emb_hi[(size_t)NUM_NODE * DIM];
__device__ __align__(16) __half g_q_hi[DIM * DIM];
__device__ __align__(16) __half g_sel_hi[N_TGT * DIM];

__device__ __forceinline__ uint32_t smem_to_u32(const void* p) {
    uint32_t a;
    asm("{ .reg .u64 t; cvta.to.shared.u64 t, %1; cvt.u32.u64 %0, t; }" : "=r"(a) : "l"(p));
    return a;
}
__device__ __forceinline__ void cp16(uint32_t daddr, const void* src, uint32_t srcsize) {
    asm volatile("cp.async.cg.shared.global [%0], [%1], 16, %2;"
                 :: "r"(daddr), "l"(src), "r"(srcsize) : "memory");
}
__device__ __forceinline__ void mma_f16(float* c, const uint32_t* a, const uint32_t* b) {
    asm volatile("mma.sync.aligned.m16n8k16.row.col.f32.f16.f16.f32 "
                 "{%0,%1,%2,%3}, {%4,%5,%6,%7}, {%8,%9}, {%0,%1,%2,%3};"
                 : "+f"(c[0]), "+f"(c[1]), "+f"(c[2]), "+f"(c[3])
                 : "r"(a[0]), "r"(a[1]), "r"(a[2]), "r"(a[3]), "r"(b[0]), "r"(b[1]));
}
__device__ __forceinline__ void ldsm4(uint32_t* r, uint32_t addr) {
    asm volatile("ldmatrix.sync.aligned.m8n8.x4.shared.b16 {%0,%1,%2,%3}, [%4];"
                 : "=r"(r[0]), "=r"(r[1]), "=r"(r[2]), "=r"(r[3]) : "r"(addr));
}
// strides: offsets mod 128 of 8 consecutive rows all-distinct -> conflict-free ldmatrix
#define RSTR  144u   // K-chunk-64 tile rows (128 B data + 16 pad)
#define ARSTR 528u   // full-K A rows (512 B data + 16 pad); 528 mod 128 = 16
__device__ __forceinline__ void ldsm_A(uint32_t* r4, uint32_t base, int row0, int kbyte, int lane, uint32_t rstr) {
    int m = lane >> 3, rr = lane & 7;
    uint32_t addr = base + (uint32_t)(row0 + ((m & 1) << 3) + rr) * rstr + kbyte + ((m >> 1) << 4);
    ldsm4(r4, addr);
}
__device__ __forceinline__ void ldsm_B(uint32_t* r4, uint32_t base, int n0, int kbyte, int lane) {
    int m = lane >> 3, rr = lane & 7;
    uint32_t addr = base + (uint32_t)(n0 + ((m >> 1) << 3) + rr) * RSTR + kbyte + ((m & 1) << 4);
    ldsm4(r4, addr);
}
__device__ __forceinline__ float fast_tanh(float x) {
    float a = __expf(2.f * x);
    return __fdividef(a - 1.f, a + 1.f);
}

// ---------------- fused prep ----------------
__global__ void k_prep(const float* __restrict__ emb, const float* __restrict__ q_w) {
    size_t i = (size_t)blockIdx.x * blockDim.x + threadIdx.x;
    if (i < (size_t)NUM_NODE * DIM) g_emb_hi[i] = __float2half(emb[i]);
    if (i < DIM * DIM) {
        int d = (int)(i >> 8), k = (int)(i & 255);
        g_q_hi[i] = __float2half(q_w[(size_t)d * (2 * DIM) + k]);
    }
    if (i < N_ITEM) g_deg[i] = 0;
    if (i < N_TGT)  g_adeg[i] = 0;
}

// ---------------- histogram ----------------
__global__ void k_hist(const int* __restrict__ i_dst, const int* __restrict__ agg_dst) {
    int i = blockIdx.x * blockDim.x + threadIdx.x;
    if (i < E_INT)  atomicAdd(&g_deg[i_dst[i]], 1);
    if (i < N_ITEM) atomicAdd(&g_adeg[agg_dst[i]], 1);
}

// ---------------- 3-phase scan ----------------
__global__ void __launch_bounds__(256) k_scanA() {
    int b = blockIdx.x, t = threadIdx.x;
    __shared__ int s[256];
    int v = (b < 320) ? g_deg[b * 256 + t] : g_adeg[(b - 320) * 256 + t];
    s[t] = v;
    __syncthreads();
    #pragma unroll
    for (int o = 128; o; o >>= 1) {
        if (t < o) s[t] += s[t + o];
        __syncthreads();
    }
    if (t == 0) g_bsum[b] = s[0];
}
__global__ void __launch_bounds__(512) k_scanB() {
    __shared__ int s[512];
    int t = threadIdx.x;
    int v = (t < 320) ? g_bsum[t] : 0;
    s[t] = v;
    __syncthreads();
    for (int o = 1; o < 512; o <<= 1) {
        int u = (t >= o) ? s[t - o] : 0;
        __syncthreads();
        if (t >= o) s[t] += u;
        __syncthreads();
    }
    if (t < 320) g_boff[t] = s[t] - v;
    if (t == 0) {
        int run = 0;
        #pragma unroll
        for (int i = 0; i < 8; i++) { g_boff[320 + i] = run; run += g_bsum[320 + i]; }
    }
}
__global__ void __launch_bounds__(256) k_scanC() {
    int b = blockIdx.x, t = threadIdx.x;
    __shared__ int s[256];
    int base = g_boff[b];
    int idx, v;
    if (b < 320) { idx = b * 256 + t; v = g_deg[idx]; }
    else         { idx = (b - 320) * 256 + t; v = g_adeg[idx]; }
    s[t] = v;
    __syncthreads();
    for (int o = 1; o < 256; o <<= 1) {
        int u = (t >= o) ? s[t - o] : 0;
        __syncthreads();
        if (t >= o) s[t] += u;
        __syncthreads();
    }
    int excl = base + s[t] - v;
    if (b < 320) { g_rowoff[idx] = excl; g_cursor[idx] = excl; }
    else         { g_arowoff[idx] = excl; g_acursor[idx] = excl; }
    if (b == 0 && t == 0) { g_rowoff[N_ITEM] = E_INT; g_arowoff[N_TGT] = N_ITEM; }
}

// ---------------- scatter ----------------
__global__ void k_scatter(const int* __restrict__ i_dst, const int* __restrict__ i_src,
                          const int* __restrict__ iid, const int* __restrict__ agg_dst) {
    int i = blockIdx.x * blockDim.x + threadIdx.x;
    if (i < E_INT) {
        int d = i_dst[i];
        int p = atomicAdd(&g_cursor[d], 1);
        g_esrc[p] = iid[i_src[i]];
    }
    if (i < N_ITEM) {
        int d = agg_dst[i];
        g_aperm[atomicAdd(&g_acursor[d], 1)] = i;
    }
}

// ---------------- single-pass attention; fp16 src gathers ----------------
__global__ void __launch_bounds__(256) k_attn(const int* __restrict__ iid,
                                              const float* __restrict__ emb,
                                              const float* __restrict__ p_w) {
    int gw   = (blockIdx.x * blockDim.x + threadIdx.x) >> 5;
    int lane = threadIdx.x & 31;
    if (gw >= N_ITEM) return;
    int v = gw;
    const float4* embv = (const float4*)emb;
    const uint4*  embh = (const uint4*)g_emb_hi;
    int c0 = lane * 2;
    size_t rv = (size_t)iid[v] * (DIM / 4);
    float4 hd0 = embv[rv + c0];
    float4 hd1 = embv[rv + c0 + 1];
    float4 pw0 = ((const float4*)p_w)[c0];
    float4 pw1 = ((const float4*)p_w)[c0 + 1];
    float hd[8] = { hd0.x*pw0.x, hd0.y*pw0.y, hd0.z*pw0.z, hd0.w*pw0.w,
                    hd1.x*pw1.x, hd1.y*pw1.y, hd1.z*pw1.z, hd1.w*pw1.w };
    int rs = g_rowoff[v], re = g_rowoff[v + 1];

    float den = 0.f;
    float acc[8] = {0.f,0.f,0.f,0.f,0.f,0.f,0.f,0.f};
    int idx = rs;
    for (; idx + 3 < re; idx += 4) {
        float f[4][8];
        float p[4];
        #pragma unroll
        for (int e = 0; e < 4; e++) {
            uint4 u = embh[(size_t)g_esrc[idx + e] * 32 + lane];
            const __half2* hp = (const __half2*)&u;
            #pragma unroll
            for (int q = 0; q < 4; q++) {
                float2 f2 = __half22float2(hp[q]);
                f[e][q*2] = f2.x; f[e][q*2+1] = f2.y;
            }
        }
        #pragma unroll
        for (int e = 0; e < 4; e++) {
            p[e] = f[e][0]*hd[0] + f[e][1]*hd[1] + f[e][2]*hd[2] + f[e][3]*hd[3]
                 + f[e][4]*hd[4] + f[e][5]*hd[5] + f[e][6]*hd[6] + f[e][7]*hd[7];
        }
        #pragma unroll
        for (int o = 16; o; o >>= 1)
            #pragma unroll
            for (int e = 0; e < 4; e++)
                p[e] += __shfl_xor_sync(0xffffffffu, p[e], o);
        #pragma unroll
        for (int e = 0; e < 4; e++) {
            float pe = (p[e] >= 0.f) ? p[e] : ALPHA * p[e];
            float ex = __expf(pe);
            den += ex;
            #pragma unroll
            for (int q = 0; q < 8; q++) acc[q] += ex * f[e][q];
        }
    }
    for (; idx < re; idx++) {
        uint4 u = embh[(size_t)g_esrc[idx] * 32 + lane];
        const __half2* hp = (const __half2*)&u;
        float f[8];
        #pragma unroll
        for (int q = 0; q < 4; q++) {
            float2 f2 = __half22float2(hp[q]);
            f[q*2] = f2.x; f[q*2+1] = f2.y;
        }
        float p = f[0]*hd[0] + f[1]*hd[1] + f[2]*hd[2] + f[3]*hd[3]
                + f[4]*hd[4] + f[5]*hd[5] + f[6]*hd[6] + f[7]*hd[7];
        #pragma unroll
        for (int o = 16; o; o >>= 1) p += __shfl_xor_sync(0xffffffffu, p, o);
        p = (p >= 0.f) ? p : ALPHA * p;
        float ex = __expf(p);
        den += ex;
        #pragma unroll
        for (int q = 0; q < 8; q++) acc[q] += ex * f[q];
    }
    float inv = 1.f / fmaxf(den, 1e-12f);
    union { __half h[8]; uint4 u; } ph;
    #pragma unroll
    for (int q = 0; q < 8; q++) ph.h[q] = __float2half(acc[q] * inv);
    ((uint4*)g_ft_hi)[(size_t)v * 32 + lane] = ph.u;
}

// ---------------- B = pos_emb @ q_w[:,256:].T ----------------
__global__ void k_posB(const float* __restrict__ pos_emb, const float* __restrict__ q_w) {
    int p = blockIdx.x, d = threadIdx.x;
    __shared__ float sp[DIM];
    sp[d] = pos_emb[p * DIM + d];
    __syncthreads();
    const float4* q4 = (const float4*)(q_w + (size_t)d * (2 * DIM) + DIM);
    float acc = 0.f;
    #pragma unroll 8
    for (int k = 0; k < DIM / 4; k++) {
        float4 q = q4[k];
        acc += sp[4*k]*q.x + sp[4*k+1]*q.y + sp[4*k+2]*q.z + sp[4*k+3]*q.w;
    }
    g_B[p * DIM + d] = acc;
}

// ======= coef GEMM constants: K-chunk 64, 2-stage (R14 proven) =======
#define ASZ (128 * RSTR)          // 18432 B per array per stage
#define STG (2 * ASZ)             // 36864 (A, B)
#define SMEM_CG (2 * STG)         // 73728
#define OFF_SJ   SMEM_CG
#define OFF_SPID (OFF_SJ + 512)
#define OFF_ST   (OFF_SPID + 512)
#define SMEM_C   (OFF_ST + 512)

__global__ void __launch_bounds__(256, 2) k_coef_mma(const int* __restrict__ agg_src,
                                                     const int* __restrict__ pid,
                                                     const int* __restrict__ agg_dst,
                                                     const int* __restrict__ tid,
                                                     const float* __restrict__ tgt_emb) {
    extern __shared__ char smc[];
    uint32_t sb = smem_to_u32(smc);
    int* sj   = (int*)(smc + OFF_SJ);
    int* spid = (int*)(smc + OFF_SPID);
    int* stt  = (int*)(smc + OFF_ST);

    int t = threadIdx.x, lane = t & 31, wid = t >> 5;
    int wm = wid & 3, wn = wid >> 2;
    int bn = blockIdx.x * 128;
    int j0 = blockIdx.y * 128;

    if (t < 128) {
        sj[t]   = agg_src[j0 + t];
        spid[t] = pid[j0 + t];
        stt[t]  = tid[agg_dst[j0 + t]];
    }
    __syncthreads();

    const uint4* Fh4 = (const uint4*)g_ft_hi;
    const uint4* Qh4 = (const uint4*)g_q_hi;

    auto prefetch = [&](int stage, int kc) {
        for (int i = t; i < 2048; i += 256) {
            int arr = i >> 10;
            int r   = (i >> 3) & 127;
            int v   = i & 7;
            uint32_t daddr = sb + stage * STG + arr * ASZ + r * RSTR + v * 16;
            if (arr == 0) {
                cp16(daddr, Fh4 + ((size_t)sj[r] * 32 + kc * 8 + v), 16);
            } else {
                cp16(daddr, Qh4 + ((size_t)(bn + r) * 32 + kc * 8 + v), 16);
            }
        }
        asm volatile("cp.async.commit_group;" ::: "memory");
    };

    float c[2][8][4];
    #pragma unroll
    for (int mt = 0; mt < 2; mt++)
        #pragma unroll
        for (int nt = 0; nt < 8; nt++)
            #pragma unroll
            for (int q = 0; q < 4; q++) c[mt][nt][q] = 0.f;

    prefetch(0, 0);
    for (int kc = 0; kc < 4; kc++) {
        asm volatile("cp.async.wait_group 0;" ::: "memory");
        __syncthreads();
        int s = kc & 1;
        if (kc + 1 < 4) prefetch(1 - s, kc + 1);
        uint32_t sA = sb + s * STG;
        uint32_t sB = sA + ASZ;
        #pragma unroll
        for (int ks = 0; ks < 4; ks++) {
            int kbyte = ks * 32;
            uint32_t ah[2][4], bh[4][4];
            ldsm_A(ah[0], sA, wm*32,      kbyte, lane, RSTR);
            ldsm_A(ah[1], sA, wm*32 + 16, kbyte, lane, RSTR);
            #pragma unroll
            for (int g = 0; g < 4; g++)
                ldsm_B(bh[g], sB, wn*64 + g*16, kbyte, lane);
            #pragma unroll
            for (int mt = 0; mt < 2; mt++)
                #pragma unroll
                for (int nt = 0; nt < 8; nt++)
                    mma_f16(c[mt][nt], ah[mt], &bh[nt >> 1][(nt & 1) * 2]);
        }
    }

    int slot = blockIdx.x * 2 + wn;
    #pragma unroll
    for (int mt = 0; mt < 2; mt++)
        #pragma unroll
        for (int half = 0; half < 2; half++) {
            int rl = wm*32 + mt*16 + half*8 + (lane >> 2);
            const float* Brow = g_B + (size_t)spid[rl] * DIM + bn;
            const float* htr  = tgt_emb + (size_t)stt[rl] * DIM + bn;
            float p = 0.f;
            #pragma unroll
            for (int nt = 0; nt < 8; nt++) {
                int cl = wn*64 + nt*8 + (lane & 3)*2;
                float y0 = c[mt][nt][half*2 + 0] + Brow[cl];
                float y1 = c[mt][nt][half*2 + 1] + Brow[cl + 1];
                p += fast_tanh(y0) * htr[cl] + fast_tanh(y1) * htr[cl + 1];
            }
            p += __shfl_xor_sync(0xffffffffu, p, 1);
            p += __shfl_xor_sync(0xffffffffu, p, 2);
            if ((lane & 3) == 0) g_cpart[slot][j0 + rl] = p;
        }
}

// ---------------- select ----------------
__global__ void k_select(const int* __restrict__ agg_src) {
    int tgt = blockIdx.x;
    int d = threadIdx.x;
    float acc = 0.f;
    int rs = g_arowoff[tgt], re = g_arowoff[tgt + 1];
    for (int idx = rs; idx < re; idx++) {
        int j = g_aperm[idx];
        float coef = (g_cpart[0][j] + g_cpart[1][j]) + (g_cpart[2][j] + g_cpart[3][j]);
        acc += coef * __half2float(g_ft_hi[(size_t)agg_src[j] * DIM + d]);
    }
    g_sel_hi[tgt * DIM + d] = __float2half(acc);
}

// ======= persistent scores: full-A resident, B streamed K-chunk 64 =======
#define A_SZ   (128 * ARSTR)          // 67584
#define PB_OFF A_SZ                    // two B stage buffers follow A
#define SMEM_P (A_SZ + 2 * ASZ)        // 104448
#define NTN 391                        // ceil(49999/128)
#define NTILES (16 * NTN)              // 6256
#define PGRID 296                      // 148 SMs x 2 CTAs

__global__ void __launch_bounds__(256, 2) k_scores_mma(float* __restrict__ out) {
    extern __shared__ char sms[];
    uint32_t sb = smem_to_u32(sms);
    int t = threadIdx.x, lane = t & 31, wid = t >> 5;
    int wm = wid & 3, wn = wid >> 2;
    const int NC = NUM_NODE - 1;

    const uint4* Ah4 = (const uint4*)g_sel_hi;
    const uint4* Bh4 = (const uint4*)g_emb_hi;

    auto loadA = [&](int bm) {
        for (int i = t; i < 4096; i += 256) {
            int r = i >> 5, v = i & 31;
            cp16(sb + r * ARSTR + v * 16, Ah4 + ((size_t)(bm + r) * 32 + v), 16);
        }
        asm volatile("cp.async.commit_group;" ::: "memory");
    };
    auto prefetchB = [&](int stage, int kc, int bn) {
        for (int i = t; i < 1024; i += 256) {
            int r = i >> 3, v = i & 7;
            int er = bn + r + 1;
            size_t off = (size_t)(er < NUM_NODE ? er : 0) * 32 + kc * 8 + v;
            cp16(sb + PB_OFF + stage * ASZ + r * RSTR + v * 16, Bh4 + off,
                 er < NUM_NODE ? 16u : 0u);
        }
        asm volatile("cp.async.commit_group;" ::: "memory");
    };

    int per = (NTILES + PGRID - 1) / PGRID;   // 22
    int t0 = blockIdx.x * per;
    int t1 = t0 + per; if (t1 > NTILES) t1 = NTILES;
    int prev_bm = -1;

    for (int tile = t0; tile < t1; tile++) {
        int bm = (tile / NTN) * 128;
        int bn = (tile % NTN) * 128;
        if (bm != prev_bm) {
            __syncthreads();              // all warps done reading old A
            loadA(bm);
            prev_bm = bm;
        }
        prefetchB(0, 0, bn);

        float c[2][8][4];
        #pragma unroll
        for (int mt = 0; mt < 2; mt++)
            #pragma unroll
            for (int nt = 0; nt < 8; nt++)
                #pragma unroll
                for (int q = 0; q < 4; q++) c[mt][nt][q] = 0.f;

        for (int kc = 0; kc < 4; kc++) {
            asm volatile("cp.async.wait_group 0;" ::: "memory");
            __syncthreads();
            int s = kc & 1;
            if (kc + 1 < 4) prefetchB(1 - s, kc + 1, bn);
            uint32_t sB = sb + PB_OFF + s * ASZ;
            #pragma unroll
            for (int ks = 0; ks < 4; ks++) {
                int kbyteB = ks * 32;
                int kbyteA = kc * 128 + ks * 32;
                uint32_t ah[2][4], bh[4][4];
                ldsm_A(ah[0], sb, wm*32,      kbyteA, lane, ARSTR);
                ldsm_A(ah[1], sb, wm*32 + 16, kbyteA, lane, ARSTR);
                #pragma unroll
                for (int g = 0; g < 4; g++)
                    ldsm_B(bh[g], sB, wn*64 + g*16, kbyteB, lane);
                #pragma unroll
                for (int mt = 0; mt < 2; mt++)
                    #pragma unroll
                    for (int nt = 0; nt < 8; nt++)
                        mma_f16(c[mt][nt], ah[mt], &bh[nt >> 1][(nt & 1) * 2]);
            }
        }

        #pragma unroll
        for (int mt = 0; mt < 2; mt++) {
            int r0 = bm + wm * 32 + mt * 16 + (lane >> 2);
            #pragma unroll
            for (int nt = 0; nt < 8; nt++) {
                int cc = bn + wn * 64 + nt * 8 + (lane & 3) * 2;
                size_t b0 = (size_t)r0 * NC + cc;
                size_t b1 = (size_t)(r0 + 8) * NC + cc;
                if (cc + 1 < NC) {
                    __stcs(&out[b0], c[mt][nt][0]); __stcs(&out[b0 + 1], c[mt][nt][1]);
                    __stcs(&out[b1], c[mt][nt][2]); __stcs(&out[b1 + 1], c[mt][nt][3]);
                } else if (cc < NC) {
                    __stcs(&out[b0], c[mt][nt][0]);
                    __stcs(&out[b1], c[mt][nt][2]);
                }
            }
        }
    }
}

// ---------------- launch ----------------
extern "C" void kernel_launch(void* const* d_in, const int* in_sizes, int n_in,
                              void* d_out, int out_size) {
    const int*   iid     = (const int*)d_in[2];
    const int*   pid     = (const int*)d_in[3];
    const int*   tidp    = (const int*)d_in[4];
    const int*   i_src   = (const int*)d_in[5];
    const int*   i_dst   = (const int*)d_in[6];
    const int*   agg_src = (const int*)d_in[7];
    const int*   agg_dst = (const int*)d_in[8];
    const float* emb     = (const float*)d_in[9];
    const float* pos_emb = (const float*)d_in[10];
    const float* tgt_emb = (const float*)d_in[11];
    const float* p_w     = (const float*)d_in[12];
    const float* q_w     = (const float*)d_in[13];
    float* out = (float*)d_out;

    static bool attr_set = false;
    if (!attr_set) {
        cudaFuncSetAttribute(k_scores_mma, cudaFuncAttributeMaxDynamicSharedMemorySize, SMEM_P);
        cudaFuncSetAttribute(k_coef_mma,   cudaFuncAttributeMaxDynamicSharedMemorySize, SMEM_C);
        attr_set = true;
    }

    k_prep    <<<(NUM_NODE * DIM + 255) / 256, 256>>>(emb, q_w);
    k_hist    <<<(E_INT + 255) / 256, 256>>>(i_dst, agg_dst);
    k_scanA   <<<328, 256>>>();
    k_scanB   <<<1, 512>>>();
    k_scanC   <<<328, 256>>>();
    k_scatter <<<(E_INT + 255) / 256, 256>>>(i_dst, i_src, iid, agg_dst);
    k_attn    <<<N_ITEM / 8, 256>>>(iid, emb, p_w);
    k_posB    <<<NPOS, 256>>>(pos_emb, q_w);
    dim3 gc(2, N_ITEM / 128);
    k_coef_mma<<<gc, 256, SMEM_C>>>(agg_src, pid, agg_dst, tidp, tgt_emb);
    k_select  <<<N_TGT, 256>>>(agg_src);
    k_scores_mma<<<PGRID, 256, SMEM_P>>>(out);
}

// round 17
// speedup vs baseline: 1.0644x; 1.0644x over previous
#include <cuda_runtime.h>
#include <cuda_fp16.h>
#include <cstdint>
#include <cstddef>

#define N_ITEM 81920
#define E_INT 327680
#define N_TGT 2048
#define NUM_NODE 50000
#define DIM 256
#define NPOS 200
#define ALPHA 0.2f

// ---------------- device scratch (static, no allocation) ----------------
__device__ __align__(16) __half g_ft_hi[(size_t)N_ITEM * DIM];
__device__ int   g_deg[N_ITEM];
__device__ int   g_rowoff[N_ITEM + 1];
__device__ int   g_cursor[N_ITEM];
__device__ int   g_esrc[E_INT];
__device__ int   g_adeg[N_TGT];
__device__ int   g_arowoff[N_TGT + 1];
__device__ int   g_acursor[N_TGT];
__device__ int   g_aperm[N_ITEM];
__device__ int   g_bsum[328];
__device__ int   g_boff[328];
__device__ __align__(16) float g_B[NPOS * DIM];
__device__ float g_cpart[4][N_ITEM];
__device__ __align__(16) __half g_emb_hi[(size_t)NUM_NODE * DIM];
__device__ __align__(16) __half g_q_hi[DIM * DIM];
__device__ __align__(16) __half g_sel_hi[N_TGT * DIM];

__device__ __forceinline__ uint32_t smem_to_u32(const void* p) {
    uint32_t a;
    asm("{ .reg .u64 t; cvta.to.shared.u64 t, %1; cvt.u32.u64 %0, t; }" : "=r"(a) : "l"(p));
    return a;
}
__device__ __forceinline__ void cp16(uint32_t daddr, const void* src, uint32_t srcsize) {
    asm volatile("cp.async.cg.shared.global [%0], [%1], 16, %2;"
                 :: "r"(daddr), "l"(src), "r"(srcsize) : "memory");
}
__device__ __forceinline__ void mma_f16(float* c, const uint32_t* a, const uint32_t* b) {
    asm volatile("mma.sync.aligned.m16n8k16.row.col.f32.f16.f16.f32 "
                 "{%0,%1,%2,%3}, {%4,%5,%6,%7}, {%8,%9}, {%0,%1,%2,%3};"
                 : "+f"(c[0]), "+f"(c[1]), "+f"(c[2]), "+f"(c[3])
                 : "r"(a[0]), "r"(a[1]), "r"(a[2]), "r"(a[3]), "r"(b[0]), "r"(b[1]));
}
__device__ __forceinline__ void ldsm4(uint32_t* r, uint32_t addr) {
    asm volatile("ldmatrix.sync.aligned.m8n8.x4.shared.b16 {%0,%1,%2,%3}, [%4];"
                 : "=r"(r[0]), "=r"(r[1]), "=r"(r[2]), "=r"(r[3]) : "r"(addr));
}
// row stride 144 B: 8-row ldmatrix offsets mod 128 all-distinct -> conflict-free
#define RSTR 144u
__device__ __forceinline__ void ldsm_A(uint32_t* r4, uint32_t base, int row0, int kbyte, int lane) {
    int m = lane >> 3, rr = lane & 7;
    uint32_t addr = base + (uint32_t)(row0 + ((m & 1) << 3) + rr) * RSTR + kbyte + ((m >> 1) << 4);
    ldsm4(r4, addr);
}
__device__ __forceinline__ void ldsm_B(uint32_t* r4, uint32_t base, int n0, int kbyte, int lane) {
    int m = lane >> 3, rr = lane & 7;
    uint32_t addr = base + (uint32_t)(n0 + ((m >> 1) << 3) + rr) * RSTR + kbyte + ((m & 1) << 4);
    ldsm4(r4, addr);
}
__device__ __forceinline__ float fast_tanh(float x) {
    float a = __expf(2.f * x);
    return __fdividef(a - 1.f, a + 1.f);
}

// ---------------- fused prep ----------------
__global__ void k_prep(const float* __restrict__ emb, const float* __restrict__ q_w) {
    size_t i = (size_t)blockIdx.x * blockDim.x + threadIdx.x;
    if (i < (size_t)NUM_NODE * DIM) g_emb_hi[i] = __float2half(emb[i]);
    if (i < DIM * DIM) {
        int d = (int)(i >> 8), k = (int)(i & 255);
        g_q_hi[i] = __float2half(q_w[(size_t)d * (2 * DIM) + k]);
    }
    if (i < N_ITEM) g_deg[i] = 0;
    if (i < N_TGT)  g_adeg[i] = 0;
}

// ---------------- histogram ----------------
__global__ void k_hist(const int* __restrict__ i_dst, const int* __restrict__ agg_dst) {
    int i = blockIdx.x * blockDim.x + threadIdx.x;
    if (i < E_INT)  atomicAdd(&g_deg[i_dst[i]], 1);
    if (i < N_ITEM) atomicAdd(&g_adeg[agg_dst[i]], 1);
}

// ---------------- 3-phase scan ----------------
__global__ void __launch_bounds__(256) k_scanA() {
    int b = blockIdx.x, t = threadIdx.x;
    __shared__ int s[256];
    int v = (b < 320) ? g_deg[b * 256 + t] : g_adeg[(b - 320) * 256 + t];
    s[t] = v;
    __syncthreads();
    #pragma unroll
    for (int o = 128; o; o >>= 1) {
        if (t < o) s[t] += s[t + o];
        __syncthreads();
    }
    if (t == 0) g_bsum[b] = s[0];
}
__global__ void __launch_bounds__(512) k_scanB() {
    __shared__ int s[512];
    int t = threadIdx.x;
    int v = (t < 320) ? g_bsum[t] : 0;
    s[t] = v;
    __syncthreads();
    for (int o = 1; o < 512; o <<= 1) {
        int u = (t >= o) ? s[t - o] : 0;
        __syncthreads();
        if (t >= o) s[t] += u;
        __syncthreads();
    }
    if (t < 320) g_boff[t] = s[t] - v;
    if (t == 0) {
        int run = 0;
        #pragma unroll
        for (int i = 0; i < 8; i++) { g_boff[320 + i] = run; run += g_bsum[320 + i]; }
    }
}
__global__ void __launch_bounds__(256) k_scanC() {
    int b = blockIdx.x, t = threadIdx.x;
    __shared__ int s[256];
    int base = g_boff[b];
    int idx, v;
    if (b < 320) { idx = b * 256 + t; v = g_deg[idx]; }
    else         { idx = (b - 320) * 256 + t; v = g_adeg[idx]; }
    s[t] = v;
    __syncthreads();
    for (int o = 1; o < 256; o <<= 1) {
        int u = (t >= o) ? s[t - o] : 0;
        __syncthreads();
        if (t >= o) s[t] += u;
        __syncthreads();
    }
    int excl = base + s[t] - v;
    if (b < 320) { g_rowoff[idx] = excl; g_cursor[idx] = excl; }
    else         { g_arowoff[idx] = excl; g_acursor[idx] = excl; }
    if (b == 0 && t == 0) { g_rowoff[N_ITEM] = E_INT; g_arowoff[N_TGT] = N_ITEM; }
}

// ---------------- scatter ----------------
__global__ void k_scatter(const int* __restrict__ i_dst, const int* __restrict__ i_src,
                          const int* __restrict__ iid, const int* __restrict__ agg_dst) {
    int i = blockIdx.x * blockDim.x + threadIdx.x;
    if (i < E_INT) {
        int d = i_dst[i];
        int p = atomicAdd(&g_cursor[d], 1);
        g_esrc[p] = iid[i_src[i]];
    }
    if (i < N_ITEM) {
        int d = agg_dst[i];
        g_aperm[atomicAdd(&g_acursor[d], 1)] = i;
    }
}

// ---------------- single-pass attention; fp16 src gathers ----------------
__global__ void __launch_bounds__(256) k_attn(const int* __restrict__ iid,
                                              const float* __restrict__ emb,
                                              const float* __restrict__ p_w) {
    int gw   = (blockIdx.x * blockDim.x + threadIdx.x) >> 5;
    int lane = threadIdx.x & 31;
    if (gw >= N_ITEM) return;
    int v = gw;
    const float4* embv = (const float4*)emb;
    const uint4*  embh = (const uint4*)g_emb_hi;
    int c0 = lane * 2;
    size_t rv = (size_t)iid[v] * (DIM / 4);
    float4 hd0 = embv[rv + c0];
    float4 hd1 = embv[rv + c0 + 1];
    float4 pw0 = ((const float4*)p_w)[c0];
    float4 pw1 = ((const float4*)p_w)[c0 + 1];
    float hd[8] = { hd0.x*pw0.x, hd0.y*pw0.y, hd0.z*pw0.z, hd0.w*pw0.w,
                    hd1.x*pw1.x, hd1.y*pw1.y, hd1.z*pw1.z, hd1.w*pw1.w };
    int rs = g_rowoff[v], re = g_rowoff[v + 1];

    float den = 0.f;
    float acc[8] = {0.f,0.f,0.f,0.f,0.f,0.f,0.f,0.f};
    int idx = rs;
    for (; idx + 3 < re; idx += 4) {
        float f[4][8];
        float p[4];
        #pragma unroll
        for (int e = 0; e < 4; e++) {
            uint4 u = embh[(size_t)g_esrc[idx + e] * 32 + lane];
            const __half2* hp = (const __half2*)&u;
            #pragma unroll
            for (int q = 0; q < 4; q++) {
                float2 f2 = __half22float2(hp[q]);
                f[e][q*2] = f2.x; f[e][q*2+1] = f2.y;
            }
        }
        #pragma unroll
        for (int e = 0; e < 4; e++) {
            p[e] = f[e][0]*hd[0] + f[e][1]*hd[1] + f[e][2]*hd[2] + f[e][3]*hd[3]
                 + f[e][4]*hd[4] + f[e][5]*hd[5] + f[e][6]*hd[6] + f[e][7]*hd[7];
        }
        #pragma unroll
        for (int o = 16; o; o >>= 1)
            #pragma unroll
            for (int e = 0; e < 4; e++)
                p[e] += __shfl_xor_sync(0xffffffffu, p[e], o);
        #pragma unroll
        for (int e = 0; e < 4; e++) {
            float pe = (p[e] >= 0.f) ? p[e] : ALPHA * p[e];
            float ex = __expf(pe);
            den += ex;
            #pragma unroll
            for (int q = 0; q < 8; q++) acc[q] += ex * f[e][q];
        }
    }
    for (; idx < re; idx++) {
        uint4 u = embh[(size_t)g_esrc[idx] * 32 + lane];
        const __half2* hp = (const __half2*)&u;
        float f[8];
        #pragma unroll
        for (int q = 0; q < 4; q++) {
            float2 f2 = __half22float2(hp[q]);
            f[q*2] = f2.x; f[q*2+1] = f2.y;
        }
        float p = f[0]*hd[0] + f[1]*hd[1] + f[2]*hd[2] + f[3]*hd[3]
                + f[4]*hd[4] + f[5]*hd[5] + f[6]*hd[6] + f[7]*hd[7];
        #pragma unroll
        for (int o = 16; o; o >>= 1) p += __shfl_xor_sync(0xffffffffu, p, o);
        p = (p >= 0.f) ? p : ALPHA * p;
        float ex = __expf(p);
        den += ex;
        #pragma unroll
        for (int q = 0; q < 8; q++) acc[q] += ex * f[q];
    }
    float inv = 1.f / fmaxf(den, 1e-12f);
    union { __half h[8]; uint4 u; } ph;
    #pragma unroll
    for (int q = 0; q < 8; q++) ph.h[q] = __float2half(acc[q] * inv);
    ((uint4*)g_ft_hi)[(size_t)v * 32 + lane] = ph.u;
}

// ---------------- B = pos_emb @ q_w[:,256:].T ----------------
__global__ void k_posB(const float* __restrict__ pos_emb, const float* __restrict__ q_w) {
    int p = blockIdx.x, d = threadIdx.x;
    __shared__ float sp[DIM];
    sp[d] = pos_emb[p * DIM + d];
    __syncthreads();
    const float4* q4 = (const float4*)(q_w + (size_t)d * (2 * DIM) + DIM);
    float acc = 0.f;
    #pragma unroll 8
    for (int k = 0; k < DIM / 4; k++) {
        float4 q = q4[k];
        acc += sp[4*k]*q.x + sp[4*k+1]*q.y + sp[4*k+2]*q.z + sp[4*k+3]*q.w;
    }
    g_B[p * DIM + d] = acc;
}

// ======= GEMM constants: K-chunk 64, 3-stage, 128x128 CTA tile =======
#define ASZ (128 * RSTR)          // 18432 B per array per stage
#define STG (2 * ASZ)             // 36864 (A, B)
#define SMEM_G (3 * STG)          // 110592
#define OFF_SJ   SMEM_G
#define OFF_SPID (OFF_SJ + 512)
#define OFF_ST   (OFF_SPID + 512)
#define SMEM_C   (OFF_ST + 512)   // 112128

// ================= k_coef (single-term fp16, K-chunk 64, 3-stage) =================
__global__ void __launch_bounds__(256, 2) k_coef_mma(const int* __restrict__ agg_src,
                                                     const int* __restrict__ pid,
                                                     const int* __restrict__ agg_dst,
                                                     const int* __restrict__ tid,
                                                     const float* __restrict__ tgt_emb) {
    extern __shared__ char smc[];
    uint32_t sb = smem_to_u32(smc);
    int* sj   = (int*)(smc + OFF_SJ);
    int* spid = (int*)(smc + OFF_SPID);
    int* stt  = (int*)(smc + OFF_ST);

    int t = threadIdx.x, lane = t & 31, wid = t >> 5;
    int wm = wid & 3, wn = wid >> 2;
    int bn = blockIdx.x * 128;
    int j0 = blockIdx.y * 128;

    if (t < 128) {
        sj[t]   = agg_src[j0 + t];
        spid[t] = pid[j0 + t];
        stt[t]  = tid[agg_dst[j0 + t]];
    }
    __syncthreads();

    const uint4* Fh4 = (const uint4*)g_ft_hi;
    const uint4* Qh4 = (const uint4*)g_q_hi;

    auto prefetch = [&](int stage, int kc) {
        for (int i = t; i < 2048; i += 256) {
            int arr = i >> 10;
            int r   = (i >> 3) & 127;
            int v   = i & 7;
            uint32_t daddr = sb + stage * STG + arr * ASZ + r * RSTR + v * 16;
            if (arr == 0) {
                cp16(daddr, Fh4 + ((size_t)sj[r] * 32 + kc * 8 + v), 16);
            } else {
                cp16(daddr, Qh4 + ((size_t)(bn + r) * 32 + kc * 8 + v), 16);
            }
        }
        asm volatile("cp.async.commit_group;" ::: "memory");
    };

    float c[2][8][4];
    #pragma unroll
    for (int mt = 0; mt < 2; mt++)
        #pragma unroll
        for (int nt = 0; nt < 8; nt++)
            #pragma unroll
            for (int q = 0; q < 4; q++) c[mt][nt][q] = 0.f;

    prefetch(0, 0);
    prefetch(1, 1);
    for (int kc = 0; kc < 4; kc++) {
        if (kc < 3) asm volatile("cp.async.wait_group 1;" ::: "memory");
        else        asm volatile("cp.async.wait_group 0;" ::: "memory");
        __syncthreads();
        if (kc + 2 < 4) prefetch((kc + 2) % 3, kc + 2);
        uint32_t sA = sb + (kc % 3) * STG;
        uint32_t sB = sA + ASZ;
        #pragma unroll
        for (int ks = 0; ks < 4; ks++) {
            int kbyte = ks * 32;
            uint32_t ah[2][4], bh[4][4];
            ldsm_A(ah[0], sA, wm*32,      kbyte, lane);
            ldsm_A(ah[1], sA, wm*32 + 16, kbyte, lane);
            #pragma unroll
            for (int g = 0; g < 4; g++)
                ldsm_B(bh[g], sB, wn*64 + g*16, kbyte, lane);
            #pragma unroll
            for (int mt = 0; mt < 2; mt++)
                #pragma unroll
                for (int nt = 0; nt < 8; nt++)
                    mma_f16(c[mt][nt], ah[mt], &bh[nt >> 1][(nt & 1) * 2]);
        }
    }

    int slot = blockIdx.x * 2 + wn;
    #pragma unroll
    for (int mt = 0; mt < 2; mt++)
        #pragma unroll
        for (int half = 0; half < 2; half++) {
            int rl = wm*32 + mt*16 + half*8 + (lane >> 2);
            const float* Brow = g_B + (size_t)spid[rl] * DIM + bn;
            const float* htr  = tgt_emb + (size_t)stt[rl] * DIM + bn;
            float p = 0.f;
            #pragma unroll
            for (int nt = 0; nt < 8; nt++) {
                int cl = wn*64 + nt*8 + (lane & 3)*2;
                float y0 = c[mt][nt][half*2 + 0] + Brow[cl];
                float y1 = c[mt][nt][half*2 + 1] + Brow[cl + 1];
                p += fast_tanh(y0) * htr[cl] + fast_tanh(y1) * htr[cl + 1];
            }
            p += __shfl_xor_sync(0xffffffffu, p, 1);
            p += __shfl_xor_sync(0xffffffffu, p, 2);
            if ((lane & 3) == 0) g_cpart[slot][j0 + rl] = p;
        }
}

// ---------------- select ----------------
__global__ void k_select(const int* __restrict__ agg_src) {
    int tgt = blockIdx.x;
    int d = threadIdx.x;
    float acc = 0.f;
    int rs = g_arowoff[tgt], re = g_arowoff[tgt + 1];
    for (int idx = rs; idx < re; idx++) {
        int j = g_aperm[idx];
        float coef = (g_cpart[0][j] + g_cpart[1][j]) + (g_cpart[2][j] + g_cpart[3][j]);
        acc += coef * __half2float(g_ft_hi[(size_t)agg_src[j] * DIM + d]);
    }
    g_sel_hi[tgt * DIM + d] = __float2half(acc);
}

// ================= scores (single-term fp16, K-chunk 64, 3-stage, streaming stores) =================
__global__ void __launch_bounds__(256, 2) k_scores_mma(float* __restrict__ out) {
    extern __shared__ char sms[];
    uint32_t sb = smem_to_u32(sms);
    int t = threadIdx.x, lane = t & 31, wid = t >> 5;
    int wm = wid & 3, wn = wid >> 2;
    int bm = blockIdx.y * 128;
    int bn = blockIdx.x * 128;
    const int NC = NUM_NODE - 1;

    const uint4* Ah4 = (const uint4*)g_sel_hi;
    const uint4* Bh4 = (const uint4*)g_emb_hi;

    auto prefetch = [&](int stage, int kc) {
        for (int i = t; i < 2048; i += 256) {
            int arr = i >> 10;
            int r   = (i >> 3) & 127;
            int v   = i & 7;
            uint32_t daddr = sb + stage * STG + arr * ASZ + r * RSTR + v * 16;
            if (arr == 0) {
                cp16(daddr, Ah4 + ((size_t)(bm + r) * 32 + kc * 8 + v), 16);
            } else {
                int er = bn + r + 1;
                size_t off = (size_t)(er < NUM_NODE ? er : 0) * 32 + kc * 8 + v;
                cp16(daddr, Bh4 + off, er < NUM_NODE ? 16u : 0u);
            }
        }
        asm volatile("cp.async.commit_group;" ::: "memory");
    };

    float c[2][8][4];
    #pragma unroll
    for (int mt = 0; mt < 2; mt++)
        #pragma unroll
        for (int nt = 0; nt < 8; nt++)
            #pragma unroll
            for (int q = 0; q < 4; q++) c[mt][nt][q] = 0.f;

    prefetch(0, 0);
    prefetch(1, 1);
    for (int kc = 0; kc < 4; kc++) {
        if (kc < 3) asm volatile("cp.async.wait_group 1;" ::: "memory");
        else        asm volatile("cp.async.wait_group 0;" ::: "memory");
        __syncthreads();
        if (kc + 2 < 4) prefetch((kc + 2) % 3, kc + 2);
        uint32_t sA = sb + (kc % 3) * STG;
        uint32_t sB = sA + ASZ;
        #pragma unroll
        for (int ks = 0; ks < 4; ks++) {
            int kbyte = ks * 32;
            uint32_t ah[2][4], bh[4][4];
            ldsm_A(ah[0], sA, wm*32,      kbyte, lane);
            ldsm_A(ah[1], sA, wm*32 + 16, kbyte, lane);
            #pragma unroll
            for (int g = 0; g < 4; g++)
                ldsm_B(bh[g], sB, wn*64 + g*16, kbyte, lane);
            #pragma unroll
            for (int mt = 0; mt < 2; mt++)
                #pragma unroll
                for (int nt = 0; nt < 8; nt++)
                    mma_f16(c[mt][nt], ah[mt], &bh[nt >> 1][(nt & 1) * 2]);
        }
    }

    #pragma unroll
    for (int mt = 0; mt < 2; mt++) {
        int r0 = bm + wm * 32 + mt * 16 + (lane >> 2);
        #pragma unroll
        for (int nt = 0; nt < 8; nt++) {
            int cc = bn + wn * 64 + nt * 8 + (lane & 3) * 2;
            size_t b0 = (size_t)r0 * NC + cc;
            size_t b1 = (size_t)(r0 + 8) * NC + cc;
            if (cc + 1 < NC) {
                __stcs(&out[b0], c[mt][nt][0]); __stcs(&out[b0 + 1], c[mt][nt][1]);
                __stcs(&out[b1], c[mt][nt][2]); __stcs(&out[b1 + 1], c[mt][nt][3]);
            } else if (cc < NC) {
                __stcs(&out[b0], c[mt][nt][0]);
                __stcs(&out[b1], c[mt][nt][2]);
            }
        }
    }
}

// ---------------- launch ----------------
extern "C" void kernel_launch(void* const* d_in, const int* in_sizes, int n_in,
                              void* d_out, int out_size) {
    const int*   iid     = (const int*)d_in[2];
    const int*   pid     = (const int*)d_in[3];
    const int*   tidp    = (const int*)d_in[4];
    const int*   i_src   = (const int*)d_in[5];
    const int*   i_dst   = (const int*)d_in[6];
    const int*   agg_src = (const int*)d_in[7];
    const int*   agg_dst = (const int*)d_in[8];
    const float* emb     = (const float*)d_in[9];
    const float* pos_emb = (const float*)d_in[10];
    const float* tgt_emb = (const float*)d_in[11];
    const float* p_w     = (const float*)d_in[12];
    const float* q_w     = (const float*)d_in[13];
    float* out = (float*)d_out;

    static bool attr_set = false;
    if (!attr_set) {
        cudaFuncSetAttribute(k_scores_mma, cudaFuncAttributeMaxDynamicSharedMemorySize, SMEM_G);
        cudaFuncSetAttribute(k_coef_mma,   cudaFuncAttributeMaxDynamicSharedMemorySize, SMEM_C);
        attr_set = true;
    }

    k_prep    <<<(NUM_NODE * DIM + 255) / 256, 256>>>(emb, q_w);
    k_hist    <<<(E_INT + 255) / 256, 256>>>(i_dst, agg_dst);
    k_scanA   <<<328, 256>>>();
    k_scanB   <<<1, 512>>>();
    k_scanC   <<<328, 256>>>();
    k_scatter <<<(E_INT + 255) / 256, 256>>>(i_dst, i_src, iid, agg_dst);
    k_attn    <<<N_ITEM / 8, 256>>>(iid, emb, p_w);
    k_posB    <<<NPOS, 256>>>(pos_emb, q_w);
    dim3 gc(2, N_ITEM / 128);
    k_coef_mma<<<gc, 256, SMEM_C>>>(agg_src, pid, agg_dst, tidp, tgt_emb);
    k_select  <<<N_TGT, 256>>>(agg_src);
    dim3 gs((NUM_NODE - 1 + 127) / 128, N_TGT / 128);
    k_scores_mma<<<gs, 256, SMEM_G>>>(out);
}